// round 16
// baseline (speedup 1.0000x reference)
#include <cuda_runtime.h>
#include <cuda_fp16.h>
#include <cuda_bf16.h>

#define D 128
#define HEADS 8
#define UNITS 16
#define MAX_NODES 50000
#define MAX_EDGES 800000
#define SCAN_BLK 1024
#define MAX_SCAN_BLOCKS ((MAX_NODES + SCAN_BLK - 1) / SCAN_BLK)

typedef unsigned long long ull;

// Scratch (device globals: no allocation allowed; zero-initialized at load)
__device__ __half g_xph[MAX_NODES * D];      // projected features, fp16, 12.8 MB
__device__ int    g_deg[MAX_NODES];          // in-degree histogram (kept zeroed)
__device__ int    g_rowptr[MAX_NODES + 1];   // CSR row pointers (by target)
__device__ int    g_cursor[MAX_NODES];       // scatter cursors
__device__ int    g_csrc[MAX_EDGES];         // CSR: source node per slot
__device__ int    g_aggval[MAX_SCAN_BLOCKS]; // lookback: block aggregates
__device__ int    g_prefval[MAX_SCAN_BLOCKS];// lookback: inclusive prefixes
__device__ int    g_state[MAX_SCAN_BLOCKS];  // lookback: 0/1/2 (kept zeroed)

// ---------------------------------------------------------------------------
// GEMM (side stream): g_xph[n][j] = fp16( sum_k x[n][k]*W[k][j] ),
// packed fma.rn.f32x2 accumulation in fp32.
// ---------------------------------------------------------------------------
__global__ void gemm_kernel(const float* __restrict__ x,
                            const float* __restrict__ W,
                            int n_nodes) {
    __shared__ ulonglong2 xs[32 * 32];  // 32 nodes x 128 floats, as 2x f32x2
    const int t = threadIdx.x;          // 0..127 output column
    const int n0 = blockIdx.x * 32;
    const int nrows = min(32, n_nodes - n0);

    const float4* x4 = reinterpret_cast<const float4*>(x);
#pragma unroll
    for (int q = 0; q < 8; q++) {
        int idx = q * 128 + t;
        int i = idx >> 5;
        int kq = idx & 31;
        float4 v = (i < nrows) ? x4[(size_t)(n0 + i) * 32 + kq]
                               : make_float4(0.f, 0.f, 0.f, 0.f);
        xs[idx] = *reinterpret_cast<ulonglong2*>(&v);
    }
    __syncthreads();

    ull acc2[32];
#pragma unroll
    for (int i = 0; i < 32; i++) acc2[i] = 0ull;  // {+0.f, +0.f}

    for (int kq = 0; kq < 32; kq++) {
        const float w0 = W[(4 * kq + 0) * D + t];
        const float w1 = W[(4 * kq + 1) * D + t];
        const float w2 = W[(4 * kq + 2) * D + t];
        const float w3 = W[(4 * kq + 3) * D + t];
        ull wp0, wp1;
        asm("mov.b64 %0, {%1,%2};" : "=l"(wp0) : "f"(w0), "f"(w1));
        asm("mov.b64 %0, {%1,%2};" : "=l"(wp1) : "f"(w2), "f"(w3));
#pragma unroll
        for (int i = 0; i < 32; i++) {
            ulonglong2 xv = xs[i * 32 + kq];  // broadcast across block
            asm("fma.rn.f32x2 %0, %1, %2, %0;" : "+l"(acc2[i]) : "l"(xv.x), "l"(wp0));
            asm("fma.rn.f32x2 %0, %1, %2, %0;" : "+l"(acc2[i]) : "l"(xv.y), "l"(wp1));
        }
    }

    for (int i = 0; i < nrows; i++) {
        float lo, hi;
        asm("mov.b64 {%0,%1}, %2;" : "=f"(lo), "=f"(hi) : "l"(acc2[i]));
        g_xph[(size_t)(n0 + i) * D + t] = __float2half_rn(lo + hi);
    }
}

// ---------------------------------------------------------------------------
// histogram of targets (int2 edge load, one edge per thread)
// ---------------------------------------------------------------------------
__global__ void hist_kernel(const int2* __restrict__ edges, int n_edges) {
    int e = blockIdx.x * blockDim.x + threadIdx.x;
    if (e >= n_edges) return;
    atomicAdd(&g_deg[edges[e].y], 1);
}

// ---------------------------------------------------------------------------
// single-pass exclusive scan (decoupled lookback); restores g_deg = 0.
// 49 blocks, all resident in wave 1 -> lookback cannot deadlock.
// ---------------------------------------------------------------------------
__global__ void scan_onepass_kernel(int n_nodes, int n_edges) {
    __shared__ int wsum[32];
    __shared__ int s_excl;
    const int tid = threadIdx.x;
    const int lane = tid & 31;
    const int warp = tid >> 5;
    const int bid = blockIdx.x;
    const int i = bid * SCAN_BLK + tid;

    int v = (i < n_nodes) ? g_deg[i] : 0;
    if (i < n_nodes) g_deg[i] = 0;   // restore for next replay

    int incl = v;
#pragma unroll
    for (int off = 1; off < 32; off <<= 1) {
        int t = __shfl_up_sync(0xFFFFFFFFu, incl, off);
        if (lane >= off) incl += t;
    }
    if (lane == 31) wsum[warp] = incl;
    __syncthreads();
    if (warp == 0) {
        int wv = wsum[lane];
        int winc = wv;
#pragma unroll
        for (int off = 1; off < 32; off <<= 1) {
            int t = __shfl_up_sync(0xFFFFFFFFu, winc, off);
            if (lane >= off) winc += t;
        }
        wsum[lane] = winc - wv;  // exclusive warp offsets
        int tot = __shfl_sync(0xFFFFFFFFu, winc, 31);
        if (lane == 0) {
            g_aggval[bid] = tot;
            __threadfence();
            atomicExch(&g_state[bid], 1);
            int excl = 0;
            for (int p = bid - 1; p >= 0;) {
                int st;
                do { st = atomicAdd(&g_state[p], 0); } while (st == 0);
                if (st == 2) { excl += atomicAdd(&g_prefval[p], 0); break; }
                excl += atomicAdd(&g_aggval[p], 0);
                p--;
            }
            g_prefval[bid] = excl + tot;
            __threadfence();
            atomicExch(&g_state[bid], 2);
            s_excl = excl;
        }
    }
    __syncthreads();

    if (i < n_nodes) {
        int r = incl - v + wsum[warp] + s_excl;
        g_rowptr[i] = r;
        g_cursor[i] = r;
    }
    if (i == 0) g_rowptr[n_nodes] = n_edges;
}

// ---------------------------------------------------------------------------
// scatter sources into CSR slots (int2, one edge per thread);
// re-zero lookback state for next replay
// ---------------------------------------------------------------------------
__global__ void scatter_kernel(const int2* __restrict__ edges, int n_edges) {
    int e = blockIdx.x * blockDim.x + threadIdx.x;
    if (e < MAX_SCAN_BLOCKS) g_state[e] = 0;
    if (e >= n_edges) return;
    int2 ed = edges[e];
    int pos = atomicAdd(&g_cursor[ed.y], 1);
    g_csrc[pos] = ed.x;
}

// ---------------------------------------------------------------------------
// fused attention: one warp per target node, HALF-WARP PER EDGE.
//   lanes 0-15 process even-slot edges, lanes 16-31 odd-slot edges;
//   each lane owns 8 features (one uint4 = 8 fp16). Head = 2 lanes -> ONE
//   shfl reduction step. 4 edges in flight per loop iteration.
//   lrelu(s) = 0.6s + 0.4|s| (exact for slope 0.2); ka pre-scaled by log2e
//   -> p = ex2(part). Tail edges: index clamped, contribution zeroed.
//   out[tgt] = gelu( (sum_e p_e * xp[src_e]) / (sum_e p_e + 1e-7) + bias )
// NO launch_bounds: natural regs; capping caused hot-loop spills (R12).
// ---------------------------------------------------------------------------
__device__ __forceinline__ float gelu_tanh(float v) {
    float c = 0.7978845608028654f * (v + 0.044715f * v * v * v);
    return 0.5f * v * (1.f + tanhf(c));
}

#define PACK2(out_, a_, b_) \
    asm("mov.b64 %0, {%1,%2};" : "=l"(out_) : "f"(a_), "f"(b_))
#define UNPACK2(a_, b_, in_) \
    asm("mov.b64 {%0,%1}, %2;" : "=f"(a_), "=f"(b_) : "l"(in_))
#define ADD2(out_, a_, b_) \
    asm("add.rn.f32x2 %0, %1, %2;" : "=l"(out_) : "l"(a_), "l"(b_))
#define MUL2(out_, a_, b_) \
    asm("mul.rn.f32x2 %0, %1, %2;" : "=l"(out_) : "l"(a_), "l"(b_))
#define FMA2(acc_, a_, b_) \
    asm("fma.rn.f32x2 %0, %1, %2, %0;" : "+l"(acc_) : "l"(a_), "l"(b_))
#define ABS2(out_, in_) \
    asm("and.b64 %0, %1, 0x7FFFFFFF7FFFFFFF;" : "=l"(out_) : "l"(in_))

__global__ void attn_kernel(const float* __restrict__ ka1,
                            const float* __restrict__ battn,
                            const float* __restrict__ bias,
                            float* __restrict__ out,
                            int n_nodes) {
    int w = (blockIdx.x * blockDim.x + threadIdx.x) >> 5;
    if (w >= n_nodes) return;
    const int lane = threadIdx.x & 31;
    const int half = lane >> 4;     // which edge of the pair
    const int hl = lane & 15;       // feature-lane within half
    const int j = hl * 8;           // first of 8 owned features

    const int row = __ldg(&g_rowptr[w]);
    const int end = __ldg(&g_rowptr[w + 1]);
    const int last = (end > row) ? (end - 1) : row;

    const uint4* xp4 = reinterpret_cast<const uint4*>(g_xph); // 8 fp16 per uint4

    // target row: 8 features
    uint4 xtu = xp4[(size_t)w * 16 + hl];
    float2 t0 = __half22float2(*reinterpret_cast<__half2*>(&xtu.x));
    float2 t1 = __half22float2(*reinterpret_cast<__half2*>(&xtu.y));
    float2 t2 = __half22float2(*reinterpret_cast<__half2*>(&xtu.z));
    float2 t3 = __half22float2(*reinterpret_cast<__half2*>(&xtu.w));

    const float4 kbA = *reinterpret_cast<const float4*>(&battn[j]);
    const float4 kbB = *reinterpret_cast<const float4*>(&battn[j + 4]);
    const float4 kaA = *reinterpret_cast<const float4*>(&ka1[j]);
    const float4 kaB = *reinterpret_cast<const float4*>(&ka1[j + 4]);

    const float LOG2E = 1.4426950408889634f;
    const float C6 = 0.6f * LOG2E, C4 = 0.4f * LOG2E;

    ull tb[4], k6[4], k4[4];
    PACK2(tb[0], t0.x + 2.f * kbA.x, t0.y + 2.f * kbA.y);
    PACK2(tb[1], t1.x + 2.f * kbA.z, t1.y + 2.f * kbA.w);
    PACK2(tb[2], t2.x + 2.f * kbB.x, t2.y + 2.f * kbB.y);
    PACK2(tb[3], t3.x + 2.f * kbB.z, t3.y + 2.f * kbB.w);
    PACK2(k6[0], C6 * kaA.x, C6 * kaA.y);
    PACK2(k6[1], C6 * kaA.z, C6 * kaA.w);
    PACK2(k6[2], C6 * kaB.x, C6 * kaB.y);
    PACK2(k6[3], C6 * kaB.z, C6 * kaB.w);
    PACK2(k4[0], C4 * kaA.x, C4 * kaA.y);
    PACK2(k4[1], C4 * kaA.z, C4 * kaA.w);
    PACK2(k4[2], C4 * kaB.x, C4 * kaB.y);
    PACK2(k4[3], C4 * kaB.z, C4 * kaB.w);

    ull acc0 = 0ull, acc1 = 0ull, acc2 = 0ull, acc3 = 0ull;
    float ssum = 0.f;

    auto process = [&](uint4 xu, bool valid) {
        float2 f0 = __half22float2(*reinterpret_cast<__half2*>(&xu.x));
        float2 f1 = __half22float2(*reinterpret_cast<__half2*>(&xu.y));
        float2 f2 = __half22float2(*reinterpret_cast<__half2*>(&xu.z));
        float2 f3 = __half22float2(*reinterpret_cast<__half2*>(&xu.w));
        ull x0, x1, x2, x3;
        PACK2(x0, f0.x, f0.y);
        PACK2(x1, f1.x, f1.y);
        PACK2(x2, f2.x, f2.y);
        PACK2(x3, f3.x, f3.y);
        ull s0, s1, s2, s3, u0, u1, u2, u3, d;
        ADD2(s0, x0, tb[0]);
        ADD2(s1, x1, tb[1]);
        ADD2(s2, x2, tb[2]);
        ADD2(s3, x3, tb[3]);
        ABS2(u0, s0);
        ABS2(u1, s1);
        ABS2(u2, s2);
        ABS2(u3, s3);
        MUL2(d, s0, k6[0]);
        FMA2(d, s1, k6[1]);
        FMA2(d, s2, k6[2]);
        FMA2(d, s3, k6[3]);
        FMA2(d, u0, k4[0]);
        FMA2(d, u1, k4[1]);
        FMA2(d, u2, k4[2]);
        FMA2(d, u3, k4[3]);
        float lo, hi;
        UNPACK2(lo, hi, d);
        float part = lo + hi;
        part += __shfl_xor_sync(0xFFFFFFFFu, part, 1);  // head = 2 lanes
        float p;
        asm("ex2.approx.ftz.f32 %0, %1;" : "=f"(p) : "f"(part));
        p = valid ? p : 0.f;
        ssum += p;
        ull pp;
        PACK2(pp, p, p);
        FMA2(acc0, pp, x0);
        FMA2(acc1, pp, x1);
        FMA2(acc2, pp, x2);
        FMA2(acc3, pp, x3);
    };

    // 4 edges per iteration: each half processes 2 (slots e+half, e+2+half)
    for (int e = row; e < end; e += 4) {
        int e0 = e + half;
        int e1 = e + 2 + half;
        int i0 = __ldg(&g_csrc[min(e0, last)]);
        int i1 = __ldg(&g_csrc[min(e1, last)]);
        uint4 v0 = xp4[(size_t)i0 * 16 + hl];
        uint4 v1 = xp4[(size_t)i1 * 16 + hl];
        process(v0, e0 < end);
        process(v1, e1 < end);
    }

    // combine the two halves (other half handled the other edge subset)
    ssum += __shfl_xor_sync(0xFFFFFFFFu, ssum, 16);
    float a0, a1, a2, a3, a4, a5, a6, a7;
    UNPACK2(a0, a1, acc0);
    UNPACK2(a2, a3, acc1);
    UNPACK2(a4, a5, acc2);
    UNPACK2(a6, a7, acc3);
    a0 += __shfl_xor_sync(0xFFFFFFFFu, a0, 16);
    a1 += __shfl_xor_sync(0xFFFFFFFFu, a1, 16);
    a2 += __shfl_xor_sync(0xFFFFFFFFu, a2, 16);
    a3 += __shfl_xor_sync(0xFFFFFFFFu, a3, 16);
    a4 += __shfl_xor_sync(0xFFFFFFFFu, a4, 16);
    a5 += __shfl_xor_sync(0xFFFFFFFFu, a5, 16);
    a6 += __shfl_xor_sync(0xFFFFFFFFu, a6, 16);
    a7 += __shfl_xor_sync(0xFFFFFFFFu, a7, 16);

    if (half == 0) {
        const float inv = 1.f / (ssum + 1e-7f);
        const float4 bA = *reinterpret_cast<const float4*>(&bias[j]);
        const float4 bB = *reinterpret_cast<const float4*>(&bias[j + 4]);
        float4 oA, oB;
        oA.x = gelu_tanh(fmaf(a0, inv, bA.x));
        oA.y = gelu_tanh(fmaf(a1, inv, bA.y));
        oA.z = gelu_tanh(fmaf(a2, inv, bA.z));
        oA.w = gelu_tanh(fmaf(a3, inv, bA.w));
        oB.x = gelu_tanh(fmaf(a4, inv, bB.x));
        oB.y = gelu_tanh(fmaf(a5, inv, bB.y));
        oB.z = gelu_tanh(fmaf(a6, inv, bB.z));
        oB.w = gelu_tanh(fmaf(a7, inv, bB.w));
        *reinterpret_cast<float4*>(&out[(size_t)w * D + j]) = oA;
        *reinterpret_cast<float4*>(&out[(size_t)w * D + j + 4]) = oB;
    }
}

// ---------------------------------------------------------------------------
extern "C" void kernel_launch(void* const* d_in, const int* in_sizes, int n_in,
                              void* d_out, int out_size) {
    const float* x     = (const float*)d_in[0];
    const int*   edges = (const int*)d_in[1];
    const float* W     = (const float*)d_in[2]; // (D, H, U) row-major == D x 128
    const float* ka1   = (const float*)d_in[3];
    const float* battn = (const float*)d_in[4];
    const float* bias  = (const float*)d_in[5];
    float* out = (float*)d_out;

    const int n_nodes = in_sizes[0] / D;
    const int n_edges = in_sizes[1] / 2;
    const int nb = (n_nodes + SCAN_BLK - 1) / SCAN_BLK;

    // One-time host-side stream/event setup (first call is the non-captured
    // correctness run; capture calls reuse these). No device allocations.
    static cudaStream_t s_side = nullptr;
    static cudaEvent_t ev_fork = nullptr, ev_join = nullptr;
    if (s_side == nullptr) {
        cudaStreamCreateWithFlags(&s_side, cudaStreamNonBlocking);
        cudaEventCreateWithFlags(&ev_fork, cudaEventDisableTiming);
        cudaEventCreateWithFlags(&ev_join, cudaEventDisableTiming);
    }

    // Fork: gemm on side stream, CSR build on main stream (independent).
    cudaEventRecord(ev_fork, 0);
    cudaStreamWaitEvent(s_side, ev_fork, 0);
    gemm_kernel<<<(n_nodes + 31) / 32, 128, 0, s_side>>>(x, W, n_nodes);
    cudaEventRecord(ev_join, s_side);

    // Main stream: in-degree histogram -> scan -> scatter
    hist_kernel<<<(n_edges + 255) / 256, 256>>>((const int2*)edges, n_edges);
    scan_onepass_kernel<<<nb, SCAN_BLK>>>(n_nodes, n_edges);
    scatter_kernel<<<(n_edges + 255) / 256, 256>>>((const int2*)edges, n_edges);

    // Join: attn needs both g_xph (gemm) and CSR (scatter)
    cudaStreamWaitEvent(0, ev_join, 0);
    {
        int threads = 128;  // finer blocks -> better occupancy granularity
        int blocks = (n_nodes * 32 + threads - 1) / threads;
        attn_kernel<<<blocks, threads>>>(ka1, battn, bias, out, n_nodes);
    }
}

// round 17
// speedup vs baseline: 1.0780x; 1.0780x over previous
#include <cuda_runtime.h>
#include <cuda_fp16.h>
#include <cuda_bf16.h>

#define D 128
#define HEADS 8
#define UNITS 16
#define MAX_NODES 50000
#define MAX_EDGES 800000
#define SCAN_BLK 1024
#define MAX_SCAN_BLOCKS ((MAX_NODES + SCAN_BLK - 1) / SCAN_BLK)

typedef unsigned long long ull;

// Scratch (device globals: no allocation allowed; zero-initialized at load)
__device__ __half g_xph[MAX_NODES * D];      // projected features, fp16, 12.8 MB
__device__ int    g_deg[MAX_NODES];          // in-degree histogram (kept zeroed)
__device__ int    g_rowptr[MAX_NODES + 1];   // CSR row pointers (by target)
__device__ int    g_cursor[MAX_NODES];       // scatter cursors
__device__ int    g_csrc[MAX_EDGES];         // CSR: source node per slot
__device__ int    g_aggval[MAX_SCAN_BLOCKS]; // lookback: block aggregates
__device__ int    g_prefval[MAX_SCAN_BLOCKS];// lookback: inclusive prefixes
__device__ int    g_state[MAX_SCAN_BLOCKS];  // lookback: 0/1/2 (kept zeroed)

// ---------------------------------------------------------------------------
// GEMM (side stream): g_xph[n][j] = fp16( sum_k x[n][k]*W[k][j] ),
// packed fma.rn.f32x2 accumulation in fp32.
// ---------------------------------------------------------------------------
__global__ void gemm_kernel(const float* __restrict__ x,
                            const float* __restrict__ W,
                            int n_nodes) {
    __shared__ ulonglong2 xs[32 * 32];  // 32 nodes x 128 floats, as 2x f32x2
    const int t = threadIdx.x;          // 0..127 output column
    const int n0 = blockIdx.x * 32;
    const int nrows = min(32, n_nodes - n0);

    const float4* x4 = reinterpret_cast<const float4*>(x);
#pragma unroll
    for (int q = 0; q < 8; q++) {
        int idx = q * 128 + t;
        int i = idx >> 5;
        int kq = idx & 31;
        float4 v = (i < nrows) ? x4[(size_t)(n0 + i) * 32 + kq]
                               : make_float4(0.f, 0.f, 0.f, 0.f);
        xs[idx] = *reinterpret_cast<ulonglong2*>(&v);
    }
    __syncthreads();

    ull acc2[32];
#pragma unroll
    for (int i = 0; i < 32; i++) acc2[i] = 0ull;  // {+0.f, +0.f}

    for (int kq = 0; kq < 32; kq++) {
        const float w0 = W[(4 * kq + 0) * D + t];
        const float w1 = W[(4 * kq + 1) * D + t];
        const float w2 = W[(4 * kq + 2) * D + t];
        const float w3 = W[(4 * kq + 3) * D + t];
        ull wp0, wp1;
        asm("mov.b64 %0, {%1,%2};" : "=l"(wp0) : "f"(w0), "f"(w1));
        asm("mov.b64 %0, {%1,%2};" : "=l"(wp1) : "f"(w2), "f"(w3));
#pragma unroll
        for (int i = 0; i < 32; i++) {
            ulonglong2 xv = xs[i * 32 + kq];  // broadcast across block
            asm("fma.rn.f32x2 %0, %1, %2, %0;" : "+l"(acc2[i]) : "l"(xv.x), "l"(wp0));
            asm("fma.rn.f32x2 %0, %1, %2, %0;" : "+l"(acc2[i]) : "l"(xv.y), "l"(wp1));
        }
    }

    for (int i = 0; i < nrows; i++) {
        float lo, hi;
        asm("mov.b64 {%0,%1}, %2;" : "=f"(lo), "=f"(hi) : "l"(acc2[i]));
        g_xph[(size_t)(n0 + i) * D + t] = __float2half_rn(lo + hi);
    }
}

// ---------------------------------------------------------------------------
// histogram of targets (int2 edge load, one edge per thread)
// ---------------------------------------------------------------------------
__global__ void hist_kernel(const int2* __restrict__ edges, int n_edges) {
    int e = blockIdx.x * blockDim.x + threadIdx.x;
    if (e >= n_edges) return;
    atomicAdd(&g_deg[edges[e].y], 1);
}

// ---------------------------------------------------------------------------
// single-pass exclusive scan (decoupled lookback); restores g_deg = 0.
// 49 blocks, all resident in wave 1 -> lookback cannot deadlock.
// ---------------------------------------------------------------------------
__global__ void scan_onepass_kernel(int n_nodes, int n_edges) {
    __shared__ int wsum[32];
    __shared__ int s_excl;
    const int tid = threadIdx.x;
    const int lane = tid & 31;
    const int warp = tid >> 5;
    const int bid = blockIdx.x;
    const int i = bid * SCAN_BLK + tid;

    int v = (i < n_nodes) ? g_deg[i] : 0;
    if (i < n_nodes) g_deg[i] = 0;   // restore for next replay

    int incl = v;
#pragma unroll
    for (int off = 1; off < 32; off <<= 1) {
        int t = __shfl_up_sync(0xFFFFFFFFu, incl, off);
        if (lane >= off) incl += t;
    }
    if (lane == 31) wsum[warp] = incl;
    __syncthreads();
    if (warp == 0) {
        int wv = wsum[lane];
        int winc = wv;
#pragma unroll
        for (int off = 1; off < 32; off <<= 1) {
            int t = __shfl_up_sync(0xFFFFFFFFu, winc, off);
            if (lane >= off) winc += t;
        }
        wsum[lane] = winc - wv;  // exclusive warp offsets
        int tot = __shfl_sync(0xFFFFFFFFu, winc, 31);
        if (lane == 0) {
            g_aggval[bid] = tot;
            __threadfence();
            atomicExch(&g_state[bid], 1);
            int excl = 0;
            for (int p = bid - 1; p >= 0;) {
                int st;
                do { st = atomicAdd(&g_state[p], 0); } while (st == 0);
                if (st == 2) { excl += atomicAdd(&g_prefval[p], 0); break; }
                excl += atomicAdd(&g_aggval[p], 0);
                p--;
            }
            g_prefval[bid] = excl + tot;
            __threadfence();
            atomicExch(&g_state[bid], 2);
            s_excl = excl;
        }
    }
    __syncthreads();

    if (i < n_nodes) {
        int r = incl - v + wsum[warp] + s_excl;
        g_rowptr[i] = r;
        g_cursor[i] = r;
    }
    if (i == 0) g_rowptr[n_nodes] = n_edges;
}

// ---------------------------------------------------------------------------
// scatter sources into CSR slots (int2, one edge per thread);
// re-zero lookback state for next replay
// ---------------------------------------------------------------------------
__global__ void scatter_kernel(const int2* __restrict__ edges, int n_edges) {
    int e = blockIdx.x * blockDim.x + threadIdx.x;
    if (e < MAX_SCAN_BLOCKS) g_state[e] = 0;
    if (e >= n_edges) return;
    int2 ed = edges[e];
    int pos = atomicAdd(&g_cursor[ed.y], 1);
    g_csrc[pos] = ed.x;
}

// ---------------------------------------------------------------------------
// fused attention: one warp per target node, MLP=8 pipelined, fp16 gathers.
//   32 lanes x 4 features (uint2 = 4 fp16 per lane) -- R15 layout, deeper.
//   lrelu(s) = 0.6s + 0.4|s|   (exact identity for slope 0.2)
//   score dot uses ka pre-scaled by {0.6,0.4}*log2e  ->  p = ex2(part)
//   out[tgt] = gelu( (sum_e p_e * xp[src_e]) / (sum_e p_e + 1e-7) + bias )
// NO launch_bounds (R12); 8 uint2 in flight = +16 regs, stays within the
// 64-reg/4-block occupancy window at 256 threads.
// ---------------------------------------------------------------------------
__device__ __forceinline__ float gelu_tanh(float v) {
    float c = 0.7978845608028654f * (v + 0.044715f * v * v * v);
    return 0.5f * v * (1.f + tanhf(c));
}

#define PACK2(out_, a_, b_) \
    asm("mov.b64 %0, {%1,%2};" : "=l"(out_) : "f"(a_), "f"(b_))
#define UNPACK2(a_, b_, in_) \
    asm("mov.b64 {%0,%1}, %2;" : "=f"(a_), "=f"(b_) : "l"(in_))
#define ADD2(out_, a_, b_) \
    asm("add.rn.f32x2 %0, %1, %2;" : "=l"(out_) : "l"(a_), "l"(b_))
#define MUL2(out_, a_, b_) \
    asm("mul.rn.f32x2 %0, %1, %2;" : "=l"(out_) : "l"(a_), "l"(b_))
#define FMA2(acc_, a_, b_) \
    asm("fma.rn.f32x2 %0, %1, %2, %0;" : "+l"(acc_) : "l"(a_), "l"(b_))
#define ABS2(out_, in_) \
    asm("and.b64 %0, %1, 0x7FFFFFFF7FFFFFFF;" : "=l"(out_) : "l"(in_))

__global__ void attn_kernel(const float* __restrict__ ka1,
                            const float* __restrict__ battn,
                            const float* __restrict__ bias,
                            float* __restrict__ out,
                            int n_nodes) {
    int w = (blockIdx.x * blockDim.x + threadIdx.x) >> 5;
    if (w >= n_nodes) return;
    const int lane = threadIdx.x & 31;
    const int j = lane * 4;

    const int row = __ldg(&g_rowptr[w]);
    const int end = __ldg(&g_rowptr[w + 1]);

    const uint2* xp2 = reinterpret_cast<const uint2*>(g_xph); // 4 halves per uint2

    // target row (fp16 -> fp32)
    uint2 xtu = xp2[(size_t)w * 32 + lane];
    float2 xt01 = __half22float2(*reinterpret_cast<__half2*>(&xtu.x));
    float2 xt23 = __half22float2(*reinterpret_cast<__half2*>(&xtu.y));
    const float4 kb = *reinterpret_cast<const float4*>(&battn[j]);
    const float4 ka = *reinterpret_cast<const float4*>(&ka1[j]);

    const float LOG2E = 1.4426950408889634f;
    // tb = xt + 2*kb, packed
    ull tb01, tb23;
    PACK2(tb01, xt01.x + 2.f * kb.x, xt01.y + 2.f * kb.y);
    PACK2(tb23, xt23.x + 2.f * kb.z, xt23.y + 2.f * kb.w);
    // ka pre-scaled: 0.6*log2e and 0.4*log2e
    ull k6_01, k6_23, k4_01, k4_23;
    PACK2(k6_01, 0.6f * LOG2E * ka.x, 0.6f * LOG2E * ka.y);
    PACK2(k6_23, 0.6f * LOG2E * ka.z, 0.6f * LOG2E * ka.w);
    PACK2(k4_01, 0.4f * LOG2E * ka.x, 0.4f * LOG2E * ka.y);
    PACK2(k4_23, 0.4f * LOG2E * ka.z, 0.4f * LOG2E * ka.w);

    ull a01 = 0ull, a23 = 0ull;  // packed accumulators {+0,+0}
    float ssum = 0.f;

    auto process = [&](uint2 xu) {
        // fp16 -> fp32 (4 converts), then packed f32x2 math
        float2 f01 = __half22float2(*reinterpret_cast<__half2*>(&xu.x));
        float2 f23 = __half22float2(*reinterpret_cast<__half2*>(&xu.y));
        ull x01, x23;
        PACK2(x01, f01.x, f01.y);
        PACK2(x23, f23.x, f23.y);
        ull s01, s23, t01, t23, d;
        ADD2(s01, x01, tb01);
        ADD2(s23, x23, tb23);
        ABS2(t01, s01);
        ABS2(t23, s23);
        MUL2(d, s01, k6_01);
        FMA2(d, s23, k6_23);
        FMA2(d, t01, k4_01);
        FMA2(d, t23, k4_23);
        float lo, hi;
        UNPACK2(lo, hi, d);
        float part = lo + hi;           // = log2e * sum_units ka*lrelu(s)
        part += __shfl_xor_sync(0xFFFFFFFFu, part, 1);
        part += __shfl_xor_sync(0xFFFFFFFFu, part, 2);
        float p;
        asm("ex2.approx.ftz.f32 %0, %1;" : "=f"(p) : "f"(part));
        ssum += p;
        ull pp;
        PACK2(pp, p, p);
        FMA2(a01, pp, x01);
        FMA2(a23, pp, x23);
    };

    int e = row;
    // deep-pipelined main loop: batch 8 indices, 8 independent 8B gathers
    for (; e + 8 <= end; e += 8) {
        int i0 = __ldg(&g_csrc[e + 0]);
        int i1 = __ldg(&g_csrc[e + 1]);
        int i2 = __ldg(&g_csrc[e + 2]);
        int i3 = __ldg(&g_csrc[e + 3]);
        int i4 = __ldg(&g_csrc[e + 4]);
        int i5 = __ldg(&g_csrc[e + 5]);
        int i6 = __ldg(&g_csrc[e + 6]);
        int i7 = __ldg(&g_csrc[e + 7]);
        uint2 v0 = xp2[(size_t)i0 * 32 + lane];
        uint2 v1 = xp2[(size_t)i1 * 32 + lane];
        uint2 v2 = xp2[(size_t)i2 * 32 + lane];
        uint2 v3 = xp2[(size_t)i3 * 32 + lane];
        uint2 v4 = xp2[(size_t)i4 * 32 + lane];
        uint2 v5 = xp2[(size_t)i5 * 32 + lane];
        uint2 v6 = xp2[(size_t)i6 * 32 + lane];
        uint2 v7 = xp2[(size_t)i7 * 32 + lane];
        process(v0);
        process(v1);
        process(v2);
        process(v3);
        process(v4);
        process(v5);
        process(v6);
        process(v7);
    }
    // 4-wide step for mid tails
    for (; e + 4 <= end; e += 4) {
        int i0 = __ldg(&g_csrc[e + 0]);
        int i1 = __ldg(&g_csrc[e + 1]);
        int i2 = __ldg(&g_csrc[e + 2]);
        int i3 = __ldg(&g_csrc[e + 3]);
        uint2 v0 = xp2[(size_t)i0 * 32 + lane];
        uint2 v1 = xp2[(size_t)i1 * 32 + lane];
        uint2 v2 = xp2[(size_t)i2 * 32 + lane];
        uint2 v3 = xp2[(size_t)i3 * 32 + lane];
        process(v0);
        process(v1);
        process(v2);
        process(v3);
    }
    for (; e < end; e++) {
        int si = __ldg(&g_csrc[e]);
        process(xp2[(size_t)si * 32 + lane]);
    }

    const float inv = 1.f / (ssum + 1e-7f);
    float a0, a1, a2, a3;
    UNPACK2(a0, a1, a01);
    UNPACK2(a2, a3, a23);
    const float4 b = *reinterpret_cast<const float4*>(&bias[j]);
    float4 o;
    o.x = gelu_tanh(fmaf(a0, inv, b.x));
    o.y = gelu_tanh(fmaf(a1, inv, b.y));
    o.z = gelu_tanh(fmaf(a2, inv, b.z));
    o.w = gelu_tanh(fmaf(a3, inv, b.w));
    *reinterpret_cast<float4*>(&out[(size_t)w * D + j]) = o;
}

// ---------------------------------------------------------------------------
extern "C" void kernel_launch(void* const* d_in, const int* in_sizes, int n_in,
                              void* d_out, int out_size) {
    const float* x     = (const float*)d_in[0];
    const int*   edges = (const int*)d_in[1];
    const float* W     = (const float*)d_in[2]; // (D, H, U) row-major == D x 128
    const float* ka1   = (const float*)d_in[3];
    const float* battn = (const float*)d_in[4];
    const float* bias  = (const float*)d_in[5];
    float* out = (float*)d_out;

    const int n_nodes = in_sizes[0] / D;
    const int n_edges = in_sizes[1] / 2;
    const int nb = (n_nodes + SCAN_BLK - 1) / SCAN_BLK;

    // One-time host-side stream/event setup (first call is the non-captured
    // correctness run; capture calls reuse these). No device allocations.
    static cudaStream_t s_side = nullptr;
    static cudaEvent_t ev_fork = nullptr, ev_join = nullptr;
    if (s_side == nullptr) {
        cudaStreamCreateWithFlags(&s_side, cudaStreamNonBlocking);
        cudaEventCreateWithFlags(&ev_fork, cudaEventDisableTiming);
        cudaEventCreateWithFlags(&ev_join, cudaEventDisableTiming);
    }

    // Fork: gemm on side stream, CSR build on main stream (independent).
    cudaEventRecord(ev_fork, 0);
    cudaStreamWaitEvent(s_side, ev_fork, 0);
    gemm_kernel<<<(n_nodes + 31) / 32, 128, 0, s_side>>>(x, W, n_nodes);
    cudaEventRecord(ev_join, s_side);

    // Main stream: in-degree histogram -> scan -> scatter
    hist_kernel<<<(n_edges + 255) / 256, 256>>>((const int2*)edges, n_edges);
    scan_onepass_kernel<<<nb, SCAN_BLK>>>(n_nodes, n_edges);
    scatter_kernel<<<(n_edges + 255) / 256, 256>>>((const int2*)edges, n_edges);

    // Join: attn needs both g_xph (gemm) and CSR (scatter)
    cudaStreamWaitEvent(0, ev_join, 0);
    {
        int threads = 256;
        int blocks = (n_nodes * 32 + threads - 1) / threads;
        attn_kernel<<<blocks, threads>>>(ka1, battn, bias, out, n_nodes);
    }
}